// round 1
// baseline (speedup 1.0000x reference)
#include <cuda_runtime.h>
#include <math.h>

// Problem constants
#define BB 4
#define TT 2048
#define DD 768
#define HH 12
#define HD 64

#define M1 (BB*TT)      // 8192
#define N1 (3*DD)       // 2304
#define K1 DD           // 768

// Scratch (alloc-free rule: __device__ globals)
__device__ float g_q[BB*HH*TT*HD];     // [b][h][t][64], pre-scaled by 1/8
__device__ float g_k[BB*HH*TT*HD];
__device__ float g_v[BB*HH*TT*HD];
__device__ float g_attn[BB*TT*DD];     // [b][t][h*64+d]

// ---------------------------------------------------------------------------
// SGEMM: 128x128x16 tile, 256 threads, 8x8 per thread in 2x2 fragments of 4x4.
// MODE 0: A = x param, epilogue scatters into g_q/g_k/g_v (+bias, Q scaled).
// MODE 1: A = g_attn (internal), epilogue writes C row-major (+bias).
// ---------------------------------------------------------------------------
template<int MODE>
__global__ __launch_bounds__(256) void sgemm_kernel(
    const float* __restrict__ A_in,
    const float* __restrict__ Bm,
    const float* __restrict__ bias,
    float* __restrict__ C,
    int M, int N, int K)
{
    __shared__ float As[16][132];   // BK x (BM+4), transposed A tile
    __shared__ float Bs[16][128];   // BK x BN

    const int tid = threadIdx.x;
    const int tx = tid & 15;
    const int ty = tid >> 4;
    const int row0 = blockIdx.y * 128;
    const int col0 = blockIdx.x * 128;

    const float* A = (MODE == 1) ? g_attn : A_in;

    float acc[8][8];
    #pragma unroll
    for (int i = 0; i < 8; i++)
        #pragma unroll
        for (int j = 0; j < 8; j++) acc[i][j] = 0.f;

    const float* Aptr = A + (long)row0 * K;
    const float* Bptr = Bm + col0;

    for (int k0 = 0; k0 < K; k0 += 16) {
        // Load A tile 128x16, store transposed into As[k][m]
        #pragma unroll
        for (int l = 0; l < 2; l++) {
            int idx = tid + l * 256;
            int ar = idx >> 2;           // 0..127
            int ac = (idx & 3) << 2;     // 0,4,8,12
            float4 v = *(const float4*)(Aptr + (long)ar * K + k0 + ac);
            As[ac + 0][ar] = v.x;
            As[ac + 1][ar] = v.y;
            As[ac + 2][ar] = v.z;
            As[ac + 3][ar] = v.w;
        }
        // Load B tile 16x128
        #pragma unroll
        for (int l = 0; l < 2; l++) {
            int idx = tid + l * 256;
            int br = idx >> 5;           // 0..15
            int bc = (idx & 31) << 2;    // 0..124
            *(float4*)(&Bs[br][bc]) = *(const float4*)(Bptr + (long)(k0 + br) * N + bc);
        }
        __syncthreads();

        #pragma unroll
        for (int kk = 0; kk < 16; kk++) {
            float a[8], b[8];
            *(float4*)&a[0] = *(const float4*)&As[kk][ty * 4];
            *(float4*)&a[4] = *(const float4*)&As[kk][64 + ty * 4];
            *(float4*)&b[0] = *(const float4*)&Bs[kk][tx * 4];
            *(float4*)&b[4] = *(const float4*)&Bs[kk][64 + tx * 4];
            #pragma unroll
            for (int i = 0; i < 8; i++)
                #pragma unroll
                for (int j = 0; j < 8; j++)
                    acc[i][j] += a[i] * b[j];
        }
        __syncthreads();
    }

    // Epilogue
    #pragma unroll
    for (int i = 0; i < 8; i++) {
        int r = row0 + ty * 4 + (i & 3) + ((i >> 2) << 6);
        #pragma unroll
        for (int j = 0; j < 8; j++) {
            int c = col0 + tx * 4 + (j & 3) + ((j >> 2) << 6);
            float v = acc[i][j] + bias[c];
            if (MODE == 0) {
                int sec = c / DD;            // 0=q,1=k,2=v (uniform per CTA)
                int d = c - sec * DD;
                int hh = d >> 6;
                int di = d & 63;
                int bb = r >> 11;            // r / 2048
                int t  = r & 2047;
                int off = (((bb * HH + hh) * TT) + t) * HD + di;
                if (sec == 0)      g_q[off] = v * 0.125f;   // 1/sqrt(64)
                else if (sec == 1) g_k[off] = v;
                else               g_v[off] = v;
            } else {
                C[(long)r * N + c] = v;
            }
        }
    }
}

// ---------------------------------------------------------------------------
// Flash attention: one CTA per (b, h, 64-row q block). 256 threads (16x16),
// each owns a 4x4 microtile. 32 K-tiles of 64 rows each. Online softmax.
// Q,K stored d-major (transposed) in smem; V natural; pitch 68 floats.
// ---------------------------------------------------------------------------
#define SP 68

__global__ __launch_bounds__(256) void attn_kernel()
{
    extern __shared__ float smem[];
    float* QsT = smem;                  // [64][SP]  QsT[d][t]
    float* KsT = QsT + 64 * SP;         // [64][SP]  KsT[d][t]
    float* Vs  = KsT + 64 * SP;         // [64][SP]  Vs[t][d]
    float* Ps  = Vs  + 64 * SP;         // [64][SP]  Ps[row][col]

    const int tid = threadIdx.x;
    const int tx = tid & 15;
    const int ty = tid >> 4;
    const int qb = blockIdx.x;          // 0..31
    const int h  = blockIdx.y;          // 0..11
    const int bb = blockIdx.z;          // 0..3

    const int bh = bb * HH + h;
    const float* Qg = g_q + ((long)bh * TT + qb * 64) * HD;
    const float* Kg = g_k + (long)bh * TT * HD;
    const float* Vg = g_v + (long)bh * TT * HD;

    // Load Q tile transposed (once)
    #pragma unroll
    for (int l = 0; l < 4; l++) {
        int idx = tid + l * 256;        // 0..1023
        int t  = idx >> 4;              // 0..63
        int d0 = (idx & 15) << 2;       // 0..60
        float4 v = *(const float4*)(Qg + t * HD + d0);
        QsT[(d0 + 0) * SP + t] = v.x;
        QsT[(d0 + 1) * SP + t] = v.y;
        QsT[(d0 + 2) * SP + t] = v.z;
        QsT[(d0 + 3) * SP + t] = v.w;
    }

    float o[4][4];
    float mi[4], li[4];
    #pragma unroll
    for (int i = 0; i < 4; i++) {
        mi[i] = -1e30f;
        li[i] = 0.f;
        #pragma unroll
        for (int j = 0; j < 4; j++) o[i][j] = 0.f;
    }

    for (int kt = 0; kt < TT / 64; kt++) {
        const float* Kt = Kg + kt * 64 * HD;
        const float* Vt = Vg + kt * 64 * HD;
        __syncthreads();   // protect Ks/Vs from previous iteration's readers
        #pragma unroll
        for (int l = 0; l < 4; l++) {
            int idx = tid + l * 256;
            int t  = idx >> 4;
            int d0 = (idx & 15) << 2;
            float4 v = *(const float4*)(Kt + t * HD + d0);
            KsT[(d0 + 0) * SP + t] = v.x;
            KsT[(d0 + 1) * SP + t] = v.y;
            KsT[(d0 + 2) * SP + t] = v.z;
            KsT[(d0 + 3) * SP + t] = v.w;
            float4 w = *(const float4*)(Vt + t * HD + d0);
            *(float4*)(Vs + t * SP + d0) = w;
        }
        __syncthreads();

        // S = Q @ K^T  (Q pre-scaled)
        float s[4][4];
        #pragma unroll
        for (int i = 0; i < 4; i++)
            #pragma unroll
            for (int j = 0; j < 4; j++) s[i][j] = 0.f;

        #pragma unroll 8
        for (int k = 0; k < 64; k++) {
            float q[4], kv[4];
            *(float4*)q  = *(const float4*)(QsT + k * SP + ty * 4);
            *(float4*)kv = *(const float4*)(KsT + k * SP + tx * 4);
            #pragma unroll
            for (int i = 0; i < 4; i++)
                #pragma unroll
                for (int j = 0; j < 4; j++)
                    s[i][j] += q[i] * kv[j];
        }

        // Online softmax (per-row; reduce across the 16 tx lanes)
        #pragma unroll
        for (int i = 0; i < 4; i++) {
            float rm = s[i][0];
            rm = fmaxf(rm, s[i][1]);
            rm = fmaxf(rm, s[i][2]);
            rm = fmaxf(rm, s[i][3]);
            #pragma unroll
            for (int off = 8; off >= 1; off >>= 1)
                rm = fmaxf(rm, __shfl_xor_sync(0xffffffffu, rm, off, 16));
            float mnew = fmaxf(mi[i], rm);
            float alpha = __expf(mi[i] - mnew);
            mi[i] = mnew;
            float rs = 0.f;
            #pragma unroll
            for (int j = 0; j < 4; j++) {
                s[i][j] = __expf(s[i][j] - mnew);
                rs += s[i][j];
            }
            #pragma unroll
            for (int off = 8; off >= 1; off >>= 1)
                rs += __shfl_xor_sync(0xffffffffu, rs, off, 16);
            li[i] = li[i] * alpha + rs;
            #pragma unroll
            for (int j = 0; j < 4; j++) o[i][j] *= alpha;
            *(float4*)(Ps + (ty * 4 + i) * SP + tx * 4) = *(float4*)s[i];
        }
        __syncthreads();

        // O += P @ V
        #pragma unroll 8
        for (int k = 0; k < 64; k++) {
            float p[4], vv[4];
            #pragma unroll
            for (int i = 0; i < 4; i++) p[i] = Ps[(ty * 4 + i) * SP + k];
            *(float4*)vv = *(const float4*)(Vs + k * SP + tx * 4);
            #pragma unroll
            for (int i = 0; i < 4; i++)
                #pragma unroll
                for (int j = 0; j < 4; j++)
                    o[i][j] += p[i] * vv[j];
        }
    }

    // Write normalized output into [b][t][h*64 + d] layout
    float* Og = g_attn + ((long)bb * TT + qb * 64) * DD + h * HD;
    #pragma unroll
    for (int i = 0; i < 4; i++) {
        float inv = 1.f / li[i];
        int t = ty * 4 + i;
        float4 r;
        r.x = o[i][0] * inv;
        r.y = o[i][1] * inv;
        r.z = o[i][2] * inv;
        r.w = o[i][3] * inv;
        *(float4*)(Og + (long)t * DD + tx * 4) = r;
    }
}

// ---------------------------------------------------------------------------
// Launch
// ---------------------------------------------------------------------------
extern "C" void kernel_launch(void* const* d_in, const int* in_sizes, int n_in,
                              void* d_out, int out_size)
{
    const float* x     = (const float*)d_in[0];
    const float* w_qkv = (const float*)d_in[1];
    const float* b_qkv = (const float*)d_in[2];
    const float* w_out = (const float*)d_in[3];
    const float* b_out = (const float*)d_in[4];
    float* out = (float*)d_out;

    (void)in_sizes; (void)n_in; (void)out_size;

    // QKV projection + scatter
    {
        dim3 grid(N1 / 128, M1 / 128);   // 18 x 64
        sgemm_kernel<0><<<grid, 256>>>(x, w_qkv, b_qkv, nullptr, M1, N1, K1);
    }

    // Flash attention
    {
        int smem_bytes = 4 * 64 * SP * (int)sizeof(float);   // 69632
        cudaFuncSetAttribute(attn_kernel,
                             cudaFuncAttributeMaxDynamicSharedMemorySize,
                             smem_bytes);
        dim3 grid(TT / 64, HH, BB);      // 32 x 12 x 4
        attn_kernel<<<grid, 256, smem_bytes>>>();
    }

    // Output projection
    {
        dim3 grid(DD / 128, M1 / 128);   // 6 x 64
        sgemm_kernel<1><<<grid, 256>>>(nullptr, w_out, b_out, out, M1, DD, DD);
    }
}

// round 3
// speedup vs baseline: 2.0750x; 2.0750x over previous
#include <cuda_runtime.h>
#include <math.h>
#include <stdint.h>

// Problem constants
#define BB 4
#define TT 2048
#define DD 768
#define HH 12
#define HD 64

#define M1 (BB*TT)      // 8192
#define N1 (3*DD)       // 2304
#define K1 DD           // 768

// Scratch (alloc-free rule: __device__ globals)
__device__ float g_q[BB*HH*TT*HD];     // [b][h][t][64], pre-scaled by 1/8
__device__ float g_k[BB*HH*TT*HD];
__device__ float g_v[BB*HH*TT*HD];
__device__ float g_attn[BB*TT*DD];     // [b][t][h*64+d]

// ---------------------------------------------------------------------------
// tf32 helpers
// ---------------------------------------------------------------------------
__device__ __forceinline__ uint32_t tf32_of(float x) {
    uint32_t u;
    asm("cvt.rna.tf32.f32 %0, %1;" : "=r"(u) : "f"(x));
    return u;
}

__device__ __forceinline__ void mma8(float* c,
                                     const uint32_t* a,
                                     const uint32_t* b) {
    asm volatile(
        "mma.sync.aligned.m16n8k8.row.col.f32.tf32.tf32.f32 "
        "{%0,%1,%2,%3}, {%4,%5,%6,%7}, {%8,%9}, {%0,%1,%2,%3};\n"
        : "+f"(c[0]), "+f"(c[1]), "+f"(c[2]), "+f"(c[3])
        : "r"(a[0]), "r"(a[1]), "r"(a[2]), "r"(a[3]),
          "r"(b[0]), "r"(b[1]));
}

// ---------------------------------------------------------------------------
// Tensor-core SGEMM: 128x128x32 tile, 256 threads (8 warps, 2x4),
// warp tile 64x32 = 4 m-frags x 4 n-frags of m16n8k8.
// MODE 0: epilogue scatters into g_q/g_k/g_v (+bias, Q scaled by 0.125)
// MODE 1: A = g_attn, epilogue writes C row-major (+bias)
// ---------------------------------------------------------------------------
#define AP 36     // A smem pitch (floats): bank = (4g+tig) -> conflict-free
#define BP 136    // B smem pitch: bank = (8*tig+g) -> conflict-free

template<int MODE>
__global__ __launch_bounds__(256) void gemm_tc(
    const float* __restrict__ A_in,
    const float* __restrict__ Bm,
    const float* __restrict__ bias,
    float* __restrict__ C,
    int M, int N, int K)
{
    __shared__ uint32_t As[128 * AP];
    __shared__ uint32_t Bs[32 * BP];

    const int tid = threadIdx.x;
    const int w = tid >> 5;
    const int lane = tid & 31;
    const int g = lane >> 2;        // 0..7
    const int tig = lane & 3;       // 0..3
    const int warp_m = w >> 2;      // 0..1
    const int warp_n = w & 3;       // 0..3
    const int row0 = blockIdx.y * 128;
    const int col0 = blockIdx.x * 128;

    const float* A = (MODE == 1) ? g_attn : A_in;
    const float* Aptr = A + (long)row0 * K;

    float acc[4][4][4];
    #pragma unroll
    for (int mf = 0; mf < 4; mf++)
        #pragma unroll
        for (int nf = 0; nf < 4; nf++)
            #pragma unroll
            for (int e = 0; e < 4; e++) acc[mf][nf][e] = 0.f;

    float4 ra[4], rb[4];

    auto load_regs = [&](int k0) {
        #pragma unroll
        for (int l = 0; l < 4; l++) {
            int id = tid + l * 256;
            int r = id >> 3;
            int c = (id & 7) << 2;
            ra[l] = *(const float4*)(Aptr + (long)r * K + k0 + c);
        }
        #pragma unroll
        for (int l = 0; l < 4; l++) {
            int id = tid + l * 256;
            int r = id >> 5;
            int c = (id & 31) << 2;
            rb[l] = *(const float4*)(Bm + (long)(k0 + r) * N + col0 + c);
        }
    };
    auto store_smem = [&]() {
        #pragma unroll
        for (int l = 0; l < 4; l++) {
            int id = tid + l * 256;
            int r = id >> 3;
            int c = (id & 7) << 2;
            As[r * AP + c + 0] = tf32_of(ra[l].x);
            As[r * AP + c + 1] = tf32_of(ra[l].y);
            As[r * AP + c + 2] = tf32_of(ra[l].z);
            As[r * AP + c + 3] = tf32_of(ra[l].w);
        }
        #pragma unroll
        for (int l = 0; l < 4; l++) {
            int id = tid + l * 256;
            int r = id >> 5;
            int c = (id & 31) << 2;
            Bs[r * BP + c + 0] = tf32_of(rb[l].x);
            Bs[r * BP + c + 1] = tf32_of(rb[l].y);
            Bs[r * BP + c + 2] = tf32_of(rb[l].z);
            Bs[r * BP + c + 3] = tf32_of(rb[l].w);
        }
    };

    const int ntiles = K / 32;
    load_regs(0);
    for (int t = 0; t < ntiles; t++) {
        store_smem();
        __syncthreads();
        if (t + 1 < ntiles) load_regs((t + 1) * 32);

        #pragma unroll
        for (int ks = 0; ks < 4; ks++) {
            const int kc = ks * 8;
            uint32_t bf[4][2];
            #pragma unroll
            for (int nf = 0; nf < 4; nf++) {
                int cn = warp_n * 32 + nf * 8 + g;
                bf[nf][0] = Bs[(kc + tig) * BP + cn];
                bf[nf][1] = Bs[(kc + tig + 4) * BP + cn];
            }
            uint32_t af[4][4];
            #pragma unroll
            for (int mf = 0; mf < 4; mf++) {
                int r0i = (warp_m * 64 + mf * 16 + g) * AP;
                int r1i = r0i + 8 * AP;
                af[mf][0] = As[r0i + kc + tig];
                af[mf][1] = As[r1i + kc + tig];
                af[mf][2] = As[r0i + kc + tig + 4];
                af[mf][3] = As[r1i + kc + tig + 4];
            }
            #pragma unroll
            for (int mf = 0; mf < 4; mf++)
                #pragma unroll
                for (int nf = 0; nf < 4; nf++)
                    mma8(acc[mf][nf], af[mf], bf[nf]);
        }
        __syncthreads();
    }

    // Epilogue
    #pragma unroll
    for (int mf = 0; mf < 4; mf++) {
        #pragma unroll
        for (int nf = 0; nf < 4; nf++) {
            #pragma unroll
            for (int e = 0; e < 4; e++) {
                int r = row0 + warp_m * 64 + mf * 16 + g + ((e >> 1) << 3);
                int c = col0 + warp_n * 32 + nf * 8 + 2 * tig + (e & 1);
                float v = acc[mf][nf][e] + bias[c];
                if (MODE == 0) {
                    int sec = c / DD;
                    int d = c - sec * DD;
                    int hh = d >> 6;
                    int di = d & 63;
                    int bb = r >> 11;
                    int tt = r & 2047;
                    int off = (((bb * HH + hh) * TT) + tt) * HD + di;
                    if (sec == 0)      g_q[off] = v * 0.125f;
                    else if (sec == 1) g_k[off] = v;
                    else               g_v[off] = v;
                } else {
                    C[(long)r * N + c] = v;
                }
            }
        }
    }
}

// ---------------------------------------------------------------------------
// Tensor-core flash attention: CTA = (b, h, 64-row q block), 128 threads
// (4 warps, each owning 16 q rows). 32 K-tiles of 64. Online softmax.
// Q fragments preloaded to registers (loop-invariant). P round-trips smem.
// ---------------------------------------------------------------------------
#define QP 68
#define KP 72

__global__ __launch_bounds__(128) void attn_tc()
{
    extern __shared__ uint32_t smn[];
    uint32_t* Qs  = smn;                 // [64][QP] row-major, tf32
    uint32_t* KsT = Qs  + 64 * QP;       // [64d][KP] K transposed
    uint32_t* Vs  = KsT + 64 * KP;       // [64t][KP] V natural
    uint32_t* Ps  = Vs  + 64 * KP;       // [64][QP] probs, tf32

    const int tid = threadIdx.x;
    const int w = tid >> 5;             // 0..3
    const int lane = tid & 31;
    const int g = lane >> 2;
    const int tig = lane & 3;
    const int qb = blockIdx.x;
    const int h  = blockIdx.y;
    const int bb = blockIdx.z;

    const int bh = bb * HH + h;
    const float* Qg = g_q + ((long)bh * TT + qb * 64) * HD;
    const float* Kg = g_k + (long)bh * TT * HD;
    const float* Vg = g_v + (long)bh * TT * HD;

    // Load Q (row-major, tf32) into smem once
    #pragma unroll
    for (int l = 0; l < 8; l++) {
        int id = tid + l * 128;
        int r = id >> 4;
        int c = (id & 15) << 2;
        float4 v = *(const float4*)(Qg + r * HD + c);
        Qs[r * QP + c + 0] = tf32_of(v.x);
        Qs[r * QP + c + 1] = tf32_of(v.y);
        Qs[r * QP + c + 2] = tf32_of(v.z);
        Qs[r * QP + c + 3] = tf32_of(v.w);
    }
    __syncthreads();

    const int qrow = w * 16 + g;

    // Preload all Q fragments (loop-invariant across K-tiles): 8 ksteps x 4
    uint32_t qa[8][4];
    {
        int r0i = qrow * QP;
        int r1i = r0i + 8 * QP;
        #pragma unroll
        for (int ks = 0; ks < 8; ks++) {
            const int kc = ks * 8;
            qa[ks][0] = Qs[r0i + kc + tig];
            qa[ks][1] = Qs[r1i + kc + tig];
            qa[ks][2] = Qs[r0i + kc + tig + 4];
            qa[ks][3] = Qs[r1i + kc + tig + 4];
        }
    }

    float o[8][4];
    #pragma unroll
    for (int nf = 0; nf < 8; nf++)
        #pragma unroll
        for (int e = 0; e < 4; e++) o[nf][e] = 0.f;
    float m0 = -1e30f, m1 = -1e30f, l0 = 0.f, l1 = 0.f;

    for (int kt = 0; kt < TT / 64; kt++) {
        const float* Kt = Kg + kt * 64 * HD;
        const float* Vt = Vg + kt * 64 * HD;
        __syncthreads();
        #pragma unroll
        for (int l = 0; l < 8; l++) {
            int id = tid + l * 128;
            int r = id >> 4;             // token 0..63
            int c = (id & 15) << 2;      // d 0..60
            float4 v = *(const float4*)(Kt + r * HD + c);
            KsT[(c + 0) * KP + r] = tf32_of(v.x);
            KsT[(c + 1) * KP + r] = tf32_of(v.y);
            KsT[(c + 2) * KP + r] = tf32_of(v.z);
            KsT[(c + 3) * KP + r] = tf32_of(v.w);
            float4 u = *(const float4*)(Vt + r * HD + c);
            Vs[r * KP + c + 0] = tf32_of(u.x);
            Vs[r * KP + c + 1] = tf32_of(u.y);
            Vs[r * KP + c + 2] = tf32_of(u.z);
            Vs[r * KP + c + 3] = tf32_of(u.w);
        }
        __syncthreads();

        // S = Q @ K^T   (k dim = d = 64, 8 ksteps)
        float s[8][4];
        #pragma unroll
        for (int nf = 0; nf < 8; nf++)
            #pragma unroll
            for (int e = 0; e < 4; e++) s[nf][e] = 0.f;

        #pragma unroll
        for (int ks = 0; ks < 8; ks++) {
            const int kc = ks * 8;
            #pragma unroll
            for (int nf = 0; nf < 8; nf++) {
                uint32_t kb[2];
                kb[0] = KsT[(kc + tig) * KP + nf * 8 + g];
                kb[1] = KsT[(kc + tig + 4) * KP + nf * 8 + g];
                mma8(s[nf], qa[ks], kb);
            }
        }

        // Online softmax: rows qrow (c0,c1) and qrow+8 (c2,c3)
        float rm0 = -1e30f, rm1 = -1e30f;
        #pragma unroll
        for (int nf = 0; nf < 8; nf++) {
            rm0 = fmaxf(rm0, fmaxf(s[nf][0], s[nf][1]));
            rm1 = fmaxf(rm1, fmaxf(s[nf][2], s[nf][3]));
        }
        #pragma unroll
        for (int off = 1; off <= 2; off <<= 1) {
            rm0 = fmaxf(rm0, __shfl_xor_sync(0xffffffffu, rm0, off));
            rm1 = fmaxf(rm1, __shfl_xor_sync(0xffffffffu, rm1, off));
        }
        float mn0 = fmaxf(m0, rm0), mn1 = fmaxf(m1, rm1);
        float al0 = __expf(m0 - mn0), al1 = __expf(m1 - mn1);
        m0 = mn0; m1 = mn1;
        float rs0 = 0.f, rs1 = 0.f;
        #pragma unroll
        for (int nf = 0; nf < 8; nf++) {
            s[nf][0] = __expf(s[nf][0] - mn0);
            s[nf][1] = __expf(s[nf][1] - mn0);
            s[nf][2] = __expf(s[nf][2] - mn1);
            s[nf][3] = __expf(s[nf][3] - mn1);
            rs0 += s[nf][0] + s[nf][1];
            rs1 += s[nf][2] + s[nf][3];
        }
        #pragma unroll
        for (int off = 1; off <= 2; off <<= 1) {
            rs0 += __shfl_xor_sync(0xffffffffu, rs0, off);
            rs1 += __shfl_xor_sync(0xffffffffu, rs1, off);
        }
        l0 = l0 * al0 + rs0;
        l1 = l1 * al1 + rs1;
        #pragma unroll
        for (int nf = 0; nf < 8; nf++) {
            o[nf][0] *= al0; o[nf][1] *= al0;
            o[nf][2] *= al1; o[nf][3] *= al1;
        }

        // Write P to smem (tf32) for the PV mma (own warp's 16 rows only)
        #pragma unroll
        for (int nf = 0; nf < 8; nf++) {
            int cbase = nf * 8 + 2 * tig;
            Ps[qrow * QP + cbase]           = tf32_of(s[nf][0]);
            Ps[qrow * QP + cbase + 1]       = tf32_of(s[nf][1]);
            Ps[(qrow + 8) * QP + cbase]     = tf32_of(s[nf][2]);
            Ps[(qrow + 8) * QP + cbase + 1] = tf32_of(s[nf][3]);
        }
        __syncwarp();

        // O += P @ V   (k dim = 64 tokens, 8 ksteps)
        #pragma unroll
        for (int ks = 0; ks < 8; ks++) {
            const int kc = ks * 8;
            uint32_t pa[4];
            int r0i = qrow * QP;
            pa[0] = Ps[r0i + kc + tig];
            pa[1] = Ps[r0i + 8 * QP + kc + tig];
            pa[2] = Ps[r0i + kc + tig + 4];
            pa[3] = Ps[r0i + 8 * QP + kc + tig + 4];
            #pragma unroll
            for (int nf = 0; nf < 8; nf++) {
                uint32_t vb[2];
                vb[0] = Vs[(kc + tig) * KP + nf * 8 + g];
                vb[1] = Vs[(kc + tig + 4) * KP + nf * 8 + g];
                mma8(o[nf], pa, vb);
            }
        }
    }

    // Write normalized output into [b][t][h*64+d]
    float inv0 = 1.f / l0;
    float inv1 = 1.f / l1;
    float* Og = g_attn + ((long)bb * TT + qb * 64) * DD + h * HD;
    #pragma unroll
    for (int nf = 0; nf < 8; nf++) {
        int cb = nf * 8 + 2 * tig;
        float2 r0v = make_float2(o[nf][0] * inv0, o[nf][1] * inv0);
        float2 r1v = make_float2(o[nf][2] * inv1, o[nf][3] * inv1);
        *(float2*)(Og + (long)qrow * DD + cb) = r0v;
        *(float2*)(Og + (long)(qrow + 8) * DD + cb) = r1v;
    }
}

// ---------------------------------------------------------------------------
// Launch
// ---------------------------------------------------------------------------
extern "C" void kernel_launch(void* const* d_in, const int* in_sizes, int n_in,
                              void* d_out, int out_size)
{
    const float* x     = (const float*)d_in[0];
    const float* w_qkv = (const float*)d_in[1];
    const float* b_qkv = (const float*)d_in[2];
    const float* w_out = (const float*)d_in[3];
    const float* b_out = (const float*)d_in[4];
    float* out = (float*)d_out;

    (void)in_sizes; (void)n_in; (void)out_size;

    // QKV projection + scatter
    {
        dim3 grid(N1 / 128, M1 / 128);   // 18 x 64
        gemm_tc<0><<<grid, 256>>>(x, w_qkv, b_qkv, nullptr, M1, N1, K1);
    }

    // Flash attention (tensor core)
    {
        int smem_bytes = (64 * QP * 2 + 64 * KP * 2) * (int)sizeof(uint32_t); // 71680
        cudaFuncSetAttribute(attn_tc,
                             cudaFuncAttributeMaxDynamicSharedMemorySize,
                             smem_bytes);
        dim3 grid(TT / 64, HH, BB);      // 32 x 12 x 4
        attn_tc<<<grid, 128, smem_bytes>>>();
    }

    // Output projection
    {
        dim3 grid(DD / 128, M1 / 128);   // 6 x 64
        gemm_tc<1><<<grid, 256>>>(nullptr, w_out, b_out, out, M1, DD, DD);
    }
}

// round 4
// speedup vs baseline: 3.0954x; 1.4918x over previous
#include <cuda_runtime.h>
#include <stdint.h>

// Problem constants
#define BB 4
#define TT 2048
#define DD 768
#define HH 12
#define HD 64

#define M1 (BB*TT)      // 8192
#define N1 (3*DD)       // 2304
#define K1 DD           // 768

// Scratch (alloc-free rule: __device__ globals). All values stored here are
// pre-rounded to tf32 (low 13 mantissa bits zero), so the MMA's RZ truncation
// of operands is lossless (== RNA rounding).
__device__ float g_q[BB*HH*TT*HD];       // [b][h][t][64], pre-scaled by 1/8
__device__ float g_k[BB*HH*TT*HD];
__device__ float g_v[BB*HH*TT*HD];
__device__ float g_attn[BB*TT*DD];       // [b][t][h*64+d], rounded
__device__ float g_xr[M1*K1];            // rounded x
__device__ float g_wqkv[K1*N1];          // rounded w_qkv
__device__ float g_wout[DD*DD];          // rounded w_out

// ---------------------------------------------------------------------------
// helpers
// ---------------------------------------------------------------------------
__device__ __forceinline__ uint32_t tf32_of(float x) {
    uint32_t u;
    asm("cvt.rna.tf32.f32 %0, %1;" : "=r"(u) : "f"(x));
    return u;
}

__device__ __forceinline__ void mma8(float* c,
                                     const uint32_t* a,
                                     const uint32_t* b) {
    asm volatile(
        "mma.sync.aligned.m16n8k8.row.col.f32.tf32.tf32.f32 "
        "{%0,%1,%2,%3}, {%4,%5,%6,%7}, {%8,%9}, {%0,%1,%2,%3};\n"
        : "+f"(c[0]), "+f"(c[1]), "+f"(c[2]), "+f"(c[3])
        : "r"(a[0]), "r"(a[1]), "r"(a[2]), "r"(a[3]),
          "r"(b[0]), "r"(b[1]));
}

__device__ __forceinline__ void cp16(uint32_t smem_dst, const void* gsrc) {
    asm volatile("cp.async.ca.shared.global [%0], [%1], 16;\n"
                 :: "r"(smem_dst), "l"(gsrc));
}
#define CP_COMMIT() asm volatile("cp.async.commit_group;\n" ::: "memory")
#define CP_WAIT(N)  asm volatile("cp.async.wait_group %0;\n" :: "n"(N) : "memory")

// ---------------------------------------------------------------------------
// Pre-round inputs to tf32 (RNA) into scratch copies
// ---------------------------------------------------------------------------
__global__ void round_tf32_kernel(const float* __restrict__ in,
                                  float* __restrict__ out, int n4) {
    int i = blockIdx.x * blockDim.x + threadIdx.x;
    if (i < n4) {
        float4 v = ((const float4*)in)[i];
        float4 r;
        r.x = __uint_as_float(tf32_of(v.x));
        r.y = __uint_as_float(tf32_of(v.y));
        r.z = __uint_as_float(tf32_of(v.z));
        r.w = __uint_as_float(tf32_of(v.w));
        ((float4*)out)[i] = r;
    }
}

// ---------------------------------------------------------------------------
// Tensor-core GEMM: 128x128x32 tile, 256 threads (8 warps 2x4), warp 64x32.
// cp.async double-buffered tiles, operands already tf32-rounded in gmem.
// MODE 0: epilogue scatters rounded into g_q (x0.125) / g_k / g_v (+bias)
// MODE 1: epilogue writes C row-major (+bias), unrounded (final output)
// ---------------------------------------------------------------------------
#define AP 36
#define BP 136
#define ASW (128*AP)    // words per A stage
#define BSW (32*BP)     // words per B stage

template<int MODE>
__global__ __launch_bounds__(256, 2) void gemm_tc(
    const float* __restrict__ A,
    const float* __restrict__ Bm,
    const float* __restrict__ bias,
    float* __restrict__ C,
    int M, int N, int K)
{
    extern __shared__ float smg[];
    uint32_t* su = (uint32_t*)smg;
    const uint32_t sbase = (uint32_t)__cvta_generic_to_shared(smg);

    const int tid = threadIdx.x;
    const int w = tid >> 5;
    const int lane = tid & 31;
    const int g = lane >> 2;
    const int tig = lane & 3;
    const int warp_m = w >> 2;
    const int warp_n = w & 3;
    const int row0 = blockIdx.y * 128;
    const int col0 = blockIdx.x * 128;

    float acc[4][4][4];
    #pragma unroll
    for (int mf = 0; mf < 4; mf++)
        #pragma unroll
        for (int nf = 0; nf < 4; nf++)
            #pragma unroll
            for (int e = 0; e < 4; e++) acc[mf][nf][e] = 0.f;

    auto issue_tile = [&](int s, int k0) {
        uint32_t abase = sbase + (s * ASW) * 4;
        #pragma unroll
        for (int l = 0; l < 4; l++) {
            int id = tid + l * 256;
            int r = id >> 3;
            int c = (id & 7) << 2;
            cp16(abase + (r * AP + c) * 4, A + (long)(row0 + r) * K + k0 + c);
        }
        uint32_t bbase = sbase + (2 * ASW + s * BSW) * 4;
        #pragma unroll
        for (int l = 0; l < 4; l++) {
            int id = tid + l * 256;
            int r = id >> 5;
            int c = (id & 31) << 2;
            cp16(bbase + (r * BP + c) * 4, Bm + (long)(k0 + r) * N + col0 + c);
        }
    };

    const int ntiles = K / 32;
    issue_tile(0, 0);
    CP_COMMIT();

    for (int t = 0; t < ntiles; t++) {
        if (t + 1 < ntiles) {
            issue_tile((t + 1) & 1, (t + 1) * 32);
            CP_COMMIT();
            CP_WAIT(1);
        } else {
            CP_WAIT(0);
        }
        __syncthreads();

        const uint32_t* As = su + (t & 1) * ASW;
        const uint32_t* Bs = su + 2 * ASW + (t & 1) * BSW;

        #pragma unroll
        for (int ks = 0; ks < 4; ks++) {
            const int kc = ks * 8;
            uint32_t bf[4][2];
            #pragma unroll
            for (int nf = 0; nf < 4; nf++) {
                int cn = warp_n * 32 + nf * 8 + g;
                bf[nf][0] = Bs[(kc + tig) * BP + cn];
                bf[nf][1] = Bs[(kc + tig + 4) * BP + cn];
            }
            uint32_t af[4][4];
            #pragma unroll
            for (int mf = 0; mf < 4; mf++) {
                int r0i = (warp_m * 64 + mf * 16 + g) * AP;
                int r1i = r0i + 8 * AP;
                af[mf][0] = As[r0i + kc + tig];
                af[mf][1] = As[r1i + kc + tig];
                af[mf][2] = As[r0i + kc + tig + 4];
                af[mf][3] = As[r1i + kc + tig + 4];
            }
            #pragma unroll
            for (int mf = 0; mf < 4; mf++)
                #pragma unroll
                for (int nf = 0; nf < 4; nf++)
                    mma8(acc[mf][nf], af[mf], bf[nf]);
        }
        __syncthreads();
    }

    // Epilogue
    #pragma unroll
    for (int mf = 0; mf < 4; mf++) {
        #pragma unroll
        for (int nf = 0; nf < 4; nf++) {
            #pragma unroll
            for (int e = 0; e < 4; e++) {
                int r = row0 + warp_m * 64 + mf * 16 + g + ((e >> 1) << 3);
                int c = col0 + warp_n * 32 + nf * 8 + 2 * tig + (e & 1);
                float v = acc[mf][nf][e] + bias[c];
                if (MODE == 0) {
                    int sec = c / DD;
                    int d = c - sec * DD;
                    int hh = d >> 6;
                    int di = d & 63;
                    int bb = r >> 11;
                    int tt = r & 2047;
                    int off = (((bb * HH + hh) * TT) + tt) * HD + di;
                    if (sec == 0)
                        g_q[off] = __uint_as_float(tf32_of(v * 0.125f));
                    else if (sec == 1)
                        g_k[off] = __uint_as_float(tf32_of(v));
                    else
                        g_v[off] = __uint_as_float(tf32_of(v));
                } else {
                    C[(long)r * N + c] = v;
                }
            }
        }
    }
}

// ---------------------------------------------------------------------------
// Flash attention: CTA = (b, h, 128-row q block), 256 threads / 8 warps,
// each warp owns 16 q rows. K-tiles of 64 tokens, cp.async double-buffered.
// All operands pre-rounded tf32; natural layouts (no transpose):
//   Qs/Ps pitch 68  (A-frag banks 4g+tig),
//   Ks    pitch 68  (B-frag banks 4g+tig),
//   Vs    pitch 72  (B-frag banks 8tig+g).
// ---------------------------------------------------------------------------
#define QP 68
#define VP 72
#define QS_OFF 0
#define PS_OFF (128*QP)                 // 8704
#define KS_OFF (2*128*QP)               // 17408
#define KSW (64*QP)                     // 4352 per stage
#define VS_OFF (KS_OFF + 2*KSW)         // 26112
#define VSW (64*VP)                     // 4608 per stage
#define SMW (VS_OFF + 2*VSW)            // 35328 words = 141312 B

__global__ __launch_bounds__(256, 1) void attn_tc()
{
    extern __shared__ float sma[];
    uint32_t* su = (uint32_t*)sma;
    const uint32_t sbase = (uint32_t)__cvta_generic_to_shared(sma);

    const int tid = threadIdx.x;
    const int w = tid >> 5;              // 0..7
    const int lane = tid & 31;
    const int g = lane >> 2;
    const int tig = lane & 3;
    const int qb = blockIdx.x;           // 0..15
    const int h  = blockIdx.y;
    const int bb = blockIdx.z;

    const int bh = bb * HH + h;
    const float* Qg = g_q + ((long)bh * TT + qb * 128) * HD;
    const float* Kg = g_k + (long)bh * TT * HD;
    const float* Vg = g_v + (long)bh * TT * HD;

    auto issue_kv = [&](int s, int kt) {
        const float* Kt = Kg + kt * 64 * HD;
        const float* Vt = Vg + kt * 64 * HD;
        uint32_t kb = sbase + (KS_OFF + s * KSW) * 4;
        uint32_t vb = sbase + (VS_OFF + s * VSW) * 4;
        #pragma unroll
        for (int l = 0; l < 4; l++) {
            int id = tid + l * 256;
            int r = id >> 4;             // 0..63
            int c = (id & 15) << 2;
            cp16(kb + (r * QP + c) * 4, Kt + r * HD + c);
            cp16(vb + (r * VP + c) * 4, Vt + r * HD + c);
        }
    };

    // Prologue: Q + tile0
    {
        uint32_t qdst = sbase + QS_OFF * 4;
        #pragma unroll
        for (int l = 0; l < 8; l++) {
            int id = tid + l * 256;
            int r = id >> 4;             // 0..127
            int c = (id & 15) << 2;
            cp16(qdst + (r * QP + c) * 4, Qg + r * HD + c);
        }
        issue_kv(0, 0);
        CP_COMMIT();
        CP_WAIT(0);
        __syncthreads();
    }

    const int qrow = w * 16 + g;

    // Preload Q fragments (loop-invariant)
    uint32_t qa[8][4];
    {
        int r0i = QS_OFF + qrow * QP;
        int r1i = r0i + 8 * QP;
        #pragma unroll
        for (int ks = 0; ks < 8; ks++) {
            const int kc = ks * 8;
            qa[ks][0] = su[r0i + kc + tig];
            qa[ks][1] = su[r1i + kc + tig];
            qa[ks][2] = su[r0i + kc + tig + 4];
            qa[ks][3] = su[r1i + kc + tig + 4];
        }
    }

    float o[8][4];
    #pragma unroll
    for (int nf = 0; nf < 8; nf++)
        #pragma unroll
        for (int e = 0; e < 4; e++) o[nf][e] = 0.f;
    float m0 = -1e30f, m1 = -1e30f, l0 = 0.f, l1 = 0.f;

    for (int kt = 0; kt < TT / 64; kt++) {
        if (kt + 1 < TT / 64) {
            issue_kv((kt + 1) & 1, kt + 1);
            CP_COMMIT();
            CP_WAIT(1);
        } else {
            CP_WAIT(0);
        }
        __syncthreads();

        const uint32_t* Ks = su + KS_OFF + (kt & 1) * KSW;
        const uint32_t* Vs = su + VS_OFF + (kt & 1) * VSW;

        // S = Q @ K^T   (k dim = d = 64)
        float s[8][4];
        #pragma unroll
        for (int nf = 0; nf < 8; nf++)
            #pragma unroll
            for (int e = 0; e < 4; e++) s[nf][e] = 0.f;

        #pragma unroll
        for (int ks = 0; ks < 8; ks++) {
            const int kc = ks * 8;
            #pragma unroll
            for (int nf = 0; nf < 8; nf++) {
                uint32_t kb[2];
                int rowi = (nf * 8 + g) * QP;
                kb[0] = Ks[rowi + kc + tig];
                kb[1] = Ks[rowi + kc + tig + 4];
                mma8(s[nf], qa[ks], kb);
            }
        }

        // Online softmax: rows qrow (c0,c1) and qrow+8 (c2,c3)
        float rm0 = -1e30f, rm1 = -1e30f;
        #pragma unroll
        for (int nf = 0; nf < 8; nf++) {
            rm0 = fmaxf(rm0, fmaxf(s[nf][0], s[nf][1]));
            rm1 = fmaxf(rm1, fmaxf(s[nf][2], s[nf][3]));
        }
        #pragma unroll
        for (int off = 1; off <= 2; off <<= 1) {
            rm0 = fmaxf(rm0, __shfl_xor_sync(0xffffffffu, rm0, off));
            rm1 = fmaxf(rm1, __shfl_xor_sync(0xffffffffu, rm1, off));
        }
        float mn0 = fmaxf(m0, rm0), mn1 = fmaxf(m1, rm1);
        float al0 = __expf(m0 - mn0), al1 = __expf(m1 - mn1);
        m0 = mn0; m1 = mn1;
        float rs0 = 0.f, rs1 = 0.f;
        #pragma unroll
        for (int nf = 0; nf < 8; nf++) {
            s[nf][0] = __expf(s[nf][0] - mn0);
            s[nf][1] = __expf(s[nf][1] - mn0);
            s[nf][2] = __expf(s[nf][2] - mn1);
            s[nf][3] = __expf(s[nf][3] - mn1);
            rs0 += s[nf][0] + s[nf][1];
            rs1 += s[nf][2] + s[nf][3];
        }
        #pragma unroll
        for (int off = 1; off <= 2; off <<= 1) {
            rs0 += __shfl_xor_sync(0xffffffffu, rs0, off);
            rs1 += __shfl_xor_sync(0xffffffffu, rs1, off);
        }
        l0 = l0 * al0 + rs0;
        l1 = l1 * al1 + rs1;
        #pragma unroll
        for (int nf = 0; nf < 8; nf++) {
            o[nf][0] *= al0; o[nf][1] *= al0;
            o[nf][2] *= al1; o[nf][3] *= al1;
        }

        // Write P (tf32-rounded) for the PV mma — own warp's rows only
        #pragma unroll
        for (int nf = 0; nf < 8; nf++) {
            int cb = nf * 8 + 2 * tig;
            su[PS_OFF + qrow * QP + cb]           = tf32_of(s[nf][0]);
            su[PS_OFF + qrow * QP + cb + 1]       = tf32_of(s[nf][1]);
            su[PS_OFF + (qrow + 8) * QP + cb]     = tf32_of(s[nf][2]);
            su[PS_OFF + (qrow + 8) * QP + cb + 1] = tf32_of(s[nf][3]);
        }
        __syncwarp();

        // O += P @ V   (k dim = 64 tokens)
        #pragma unroll
        for (int ks = 0; ks < 8; ks++) {
            const int kc = ks * 8;
            uint32_t pa[4];
            int r0i = PS_OFF + qrow * QP;
            pa[0] = su[r0i + kc + tig];
            pa[1] = su[r0i + 8 * QP + kc + tig];
            pa[2] = su[r0i + kc + tig + 4];
            pa[3] = su[r0i + 8 * QP + kc + tig + 4];
            #pragma unroll
            for (int nf = 0; nf < 8; nf++) {
                uint32_t vb[2];
                vb[0] = Vs[(kc + tig) * VP + nf * 8 + g];
                vb[1] = Vs[(kc + tig + 4) * VP + nf * 8 + g];
                mma8(o[nf], pa, vb);
            }
        }
        __syncthreads();
    }

    // Write normalized, tf32-rounded output into [b][t][h*64+d]
    float inv0 = 1.f / l0;
    float inv1 = 1.f / l1;
    float* Og = g_attn + ((long)bb * TT + qb * 128) * DD + h * HD;
    #pragma unroll
    for (int nf = 0; nf < 8; nf++) {
        int cb = nf * 8 + 2 * tig;
        float2 r0v, r1v;
        r0v.x = __uint_as_float(tf32_of(o[nf][0] * inv0));
        r0v.y = __uint_as_float(tf32_of(o[nf][1] * inv0));
        r1v.x = __uint_as_float(tf32_of(o[nf][2] * inv1));
        r1v.y = __uint_as_float(tf32_of(o[nf][3] * inv1));
        *(float2*)(Og + (long)qrow * DD + cb) = r0v;
        *(float2*)(Og + (long)(qrow + 8) * DD + cb) = r1v;
    }
}

// ---------------------------------------------------------------------------
// Launch
// ---------------------------------------------------------------------------
extern "C" void kernel_launch(void* const* d_in, const int* in_sizes, int n_in,
                              void* d_out, int out_size)
{
    const float* x     = (const float*)d_in[0];
    const float* w_qkv = (const float*)d_in[1];
    const float* b_qkv = (const float*)d_in[2];
    const float* w_out = (const float*)d_in[3];
    const float* b_out = (const float*)d_in[4];
    float* out = (float*)d_out;

    (void)in_sizes; (void)n_in; (void)out_size;

    float *xr, *wqkvr, *woutr;
    cudaGetSymbolAddress((void**)&xr, g_xr);
    cudaGetSymbolAddress((void**)&wqkvr, g_wqkv);
    cudaGetSymbolAddress((void**)&woutr, g_wout);

    // Pre-round inputs to tf32 (RNA)
    {
        int n4 = (M1 * K1) / 4;
        round_tf32_kernel<<<(n4 + 255) / 256, 256>>>(x, xr, n4);
        n4 = (K1 * N1) / 4;
        round_tf32_kernel<<<(n4 + 255) / 256, 256>>>(w_qkv, wqkvr, n4);
        n4 = (DD * DD) / 4;
        round_tf32_kernel<<<(n4 + 255) / 256, 256>>>(w_out, woutr, n4);
    }

    const int gemm_smem = (2 * ASW + 2 * BSW) * (int)sizeof(float); // 71680
    cudaFuncSetAttribute(gemm_tc<0>, cudaFuncAttributeMaxDynamicSharedMemorySize, gemm_smem);
    cudaFuncSetAttribute(gemm_tc<1>, cudaFuncAttributeMaxDynamicSharedMemorySize, gemm_smem);

    // QKV projection + scatter (pre-rounded epilogue)
    {
        dim3 grid(N1 / 128, M1 / 128);   // 18 x 64
        gemm_tc<0><<<grid, 256, gemm_smem>>>(xr, wqkvr, b_qkv, nullptr, M1, N1, K1);
    }

    // Flash attention
    {
        int smem_bytes = SMW * (int)sizeof(float);  // 141312
        cudaFuncSetAttribute(attn_tc, cudaFuncAttributeMaxDynamicSharedMemorySize, smem_bytes);
        dim3 grid(TT / 128, HH, BB);     // 16 x 12 x 4
        attn_tc<<<grid, 256, smem_bytes>>>();
    }

    // Output projection
    {
        dim3 grid(DD / 128, M1 / 128);   // 6 x 64
        float* attn_ptr;
        cudaGetSymbolAddress((void**)&attn_ptr, g_attn);
        gemm_tc<1><<<grid, 256, gemm_smem>>>(attn_ptr, woutr, b_out, out, M1, DD, DD);
    }
}

// round 6
// speedup vs baseline: 3.3726x; 1.0896x over previous
#include <cuda_runtime.h>
#include <stdint.h>

// Problem constants
#define BB 4
#define TT 2048
#define DD 768
#define HH 12
#define HD 64

#define M1 (BB*TT)      // 8192
#define N1 (3*DD)       // 2304
#define K1 DD           // 768

// Scratch (alloc-free). All values pre-rounded to tf32 so MMA RZ truncation
// is lossless.
__device__ float g_q[BB*HH*TT*HD];
__device__ float g_k[BB*HH*TT*HD];
__device__ float g_v[BB*HH*TT*HD];
__device__ float g_attn[BB*TT*DD];
__device__ float g_xr[M1*K1];
__device__ float g_wqkv[K1*N1];
__device__ float g_wout[DD*DD];

// ---------------------------------------------------------------------------
__device__ __forceinline__ uint32_t tf32_of(float x) {
    uint32_t u;
    asm("cvt.rna.tf32.f32 %0, %1;" : "=r"(u) : "f"(x));
    return u;
}

__device__ __forceinline__ void mma8(float* c,
                                     const uint32_t* a,
                                     const uint32_t* b) {
    asm volatile(
        "mma.sync.aligned.m16n8k8.row.col.f32.tf32.tf32.f32 "
        "{%0,%1,%2,%3}, {%4,%5,%6,%7}, {%8,%9}, {%0,%1,%2,%3};\n"
        : "+f"(c[0]), "+f"(c[1]), "+f"(c[2]), "+f"(c[3])
        : "r"(a[0]), "r"(a[1]), "r"(a[2]), "r"(a[3]),
          "r"(b[0]), "r"(b[1]));
}

__device__ __forceinline__ void cp16(uint32_t smem_dst, const void* gsrc) {
    asm volatile("cp.async.ca.shared.global [%0], [%1], 16;\n"
                 :: "r"(smem_dst), "l"(gsrc));
}
#define CP_COMMIT() asm volatile("cp.async.commit_group;\n" ::: "memory")
#define CP_WAIT(N)  asm volatile("cp.async.wait_group %0;\n" :: "n"(N) : "memory")

// ---------------------------------------------------------------------------
__global__ void round_tf32_kernel(const float* __restrict__ in,
                                  float* __restrict__ out, int n4) {
    int i = blockIdx.x * blockDim.x + threadIdx.x;
    if (i < n4) {
        float4 v = ((const float4*)in)[i];
        float4 r;
        r.x = __uint_as_float(tf32_of(v.x));
        r.y = __uint_as_float(tf32_of(v.y));
        r.z = __uint_as_float(tf32_of(v.z));
        r.w = __uint_as_float(tf32_of(v.w));
        ((float4*)out)[i] = r;
    }
}

// ---------------------------------------------------------------------------
// Tensor-core GEMM: CTA tile 128x256, k-chunk 32, 256 threads / 8 warps
// (2 warp_m x 4 warp_n), warp tile 64x64 (mf=4, nf=8). cp.async 2-stage.
// MODE 0: scatter rounded into g_q (x0.125) / g_k / g_v (+bias)
// MODE 1: C row-major (+bias)
// ---------------------------------------------------------------------------
#define AP 36
#define BPg 264
#define ASW (128*AP)     // 4608 words per A stage
#define BSW (32*BPg)     // 8448 words per B stage

template<int MODE>
__global__ __launch_bounds__(256, 1) void gemm_tc(
    const float* __restrict__ A,
    const float* __restrict__ Bm,
    const float* __restrict__ bias,
    float* __restrict__ C,
    int M, int N, int K)
{
    extern __shared__ float smg[];
    uint32_t* su = (uint32_t*)smg;
    const uint32_t sbase = (uint32_t)__cvta_generic_to_shared(smg);

    const int tid = threadIdx.x;
    const int w = tid >> 5;
    const int lane = tid & 31;
    const int g = lane >> 2;
    const int tig = lane & 3;
    const int warp_m = w >> 2;      // 0..1
    const int warp_n = w & 3;       // 0..3
    const int row0 = blockIdx.y * 128;
    const int col0 = blockIdx.x * 256;

    float acc[4][8][4];
    #pragma unroll
    for (int mf = 0; mf < 4; mf++)
        #pragma unroll
        for (int nf = 0; nf < 8; nf++)
            #pragma unroll
            for (int e = 0; e < 4; e++) acc[mf][nf][e] = 0.f;

    auto issue_tile = [&](int s, int k0) {
        uint32_t abase = sbase + (s * ASW) * 4;
        #pragma unroll
        for (int l = 0; l < 4; l++) {
            int id = tid + l * 256;
            int r = id >> 3;
            int c = (id & 7) << 2;
            cp16(abase + (r * AP + c) * 4, A + (long)(row0 + r) * K + k0 + c);
        }
        uint32_t bbase = sbase + (2 * ASW + s * BSW) * 4;
        #pragma unroll
        for (int l = 0; l < 8; l++) {
            int id = tid + l * 256;
            int r = id >> 6;             // 0..31
            int c = (id & 63) << 2;      // 0..252
            cp16(bbase + (r * BPg + c) * 4, Bm + (long)(k0 + r) * N + col0 + c);
        }
    };

    const int ntiles = K / 32;
    issue_tile(0, 0);
    CP_COMMIT();

    for (int t = 0; t < ntiles; t++) {
        if (t + 1 < ntiles) {
            issue_tile((t + 1) & 1, (t + 1) * 32);
            CP_COMMIT();
            CP_WAIT(1);
        } else {
            CP_WAIT(0);
        }
        __syncthreads();

        const uint32_t* As = su + (t & 1) * ASW;
        const uint32_t* Bs = su + 2 * ASW + (t & 1) * BSW;

        #pragma unroll
        for (int ks = 0; ks < 4; ks++) {
            const int kc = ks * 8;
            uint32_t bf[8][2];
            #pragma unroll
            for (int nf = 0; nf < 8; nf++) {
                int cn = warp_n * 64 + nf * 8 + g;
                bf[nf][0] = Bs[(kc + tig) * BPg + cn];
                bf[nf][1] = Bs[(kc + tig + 4) * BPg + cn];
            }
            uint32_t af[4][4];
            #pragma unroll
            for (int mf = 0; mf < 4; mf++) {
                int r0i = (warp_m * 64 + mf * 16 + g) * AP;
                int r1i = r0i + 8 * AP;
                af[mf][0] = As[r0i + kc + tig];
                af[mf][1] = As[r1i + kc + tig];
                af[mf][2] = As[r0i + kc + tig + 4];
                af[mf][3] = As[r1i + kc + tig + 4];
            }
            #pragma unroll
            for (int mf = 0; mf < 4; mf++)
                #pragma unroll
                for (int nf = 0; nf < 8; nf++)
                    mma8(acc[mf][nf], af[mf], bf[nf]);
        }
        __syncthreads();
    }

    // Epilogue — paired float2 stores
    #pragma unroll
    for (int mf = 0; mf < 4; mf++) {
        #pragma unroll
        for (int nf = 0; nf < 8; nf++) {
            #pragma unroll
            for (int eh = 0; eh < 2; eh++) {
                int r = row0 + warp_m * 64 + mf * 16 + g + (eh << 3);
                int c = col0 + warp_n * 64 + nf * 8 + 2 * tig;
                float v0 = acc[mf][nf][2 * eh]     + bias[c];
                float v1 = acc[mf][nf][2 * eh + 1] + bias[c + 1];
                if (MODE == 0) {
                    int sec = c / DD;            // constant within the pair
                    int d = c - sec * DD;
                    int hh = d >> 6;
                    int di = d & 63;
                    int bb = r >> 11;
                    int tt = r & 2047;
                    int off = (((bb * HH + hh) * TT) + tt) * HD + di;
                    float2 p;
                    if (sec == 0) {
                        p.x = __uint_as_float(tf32_of(v0 * 0.125f));
                        p.y = __uint_as_float(tf32_of(v1 * 0.125f));
                        *(float2*)(g_q + off) = p;
                    } else if (sec == 1) {
                        p.x = __uint_as_float(tf32_of(v0));
                        p.y = __uint_as_float(tf32_of(v1));
                        *(float2*)(g_k + off) = p;
                    } else {
                        p.x = __uint_as_float(tf32_of(v0));
                        p.y = __uint_as_float(tf32_of(v1));
                        *(float2*)(g_v + off) = p;
                    }
                } else {
                    float2 p = make_float2(v0, v1);
                    *(float2*)(C + (long)r * N + c) = p;
                }
            }
        }
    }
}

// ---------------------------------------------------------------------------
// Flash attention: CTA = (b, h, 128-row q block), 128 threads / 4 warps,
// warp owns 32 q-rows (mf=2). Q fully in registers; P reuses Q smem region
// (warp-private rows). K-tiles of 64 tokens, cp.async double-buffered.
//   P/Q pitch 68 (A-frag banks), Ks pitch 68 (B-frag), Vs pitch 72 (B-frag).
// ---------------------------------------------------------------------------
#define QP 68
#define VP 72
#define PQ_OFF 0
#define KS_OFF (128*QP)                 // 8704
#define KSW (64*QP)                     // 4352 per stage
#define VS_OFF (KS_OFF + 2*KSW)        // 17408
#define VSW (64*VP)                     // 4608 per stage
#define SMW (VS_OFF + 2*VSW)           // 26624 words = 106496 B

__global__ __launch_bounds__(128, 2) void attn_tc()
{
    extern __shared__ float sma[];
    uint32_t* su = (uint32_t*)sma;
    const uint32_t sbase = (uint32_t)__cvta_generic_to_shared(sma);

    const int tid = threadIdx.x;
    const int w = tid >> 5;              // 0..3
    const int lane = tid & 31;
    const int g = lane >> 2;
    const int tig = lane & 3;
    const int qb = blockIdx.x;           // 0..15
    const int h  = blockIdx.y;
    const int bb = blockIdx.z;

    const int bh = bb * HH + h;
    const float* Qg = g_q + ((long)bh * TT + qb * 128) * HD;
    const float* Kg = g_k + (long)bh * TT * HD;
    const float* Vg = g_v + (long)bh * TT * HD;

    auto issue_kv = [&](int s, int kt) {
        const float* Kt = Kg + kt * 64 * HD;
        const float* Vt = Vg + kt * 64 * HD;
        uint32_t kb = sbase + (KS_OFF + s * KSW) * 4;
        uint32_t vb = sbase + (VS_OFF + s * VSW) * 4;
        #pragma unroll
        for (int l = 0; l < 8; l++) {
            int id = tid + l * 128;
            int r = id >> 4;             // 0..63
            int c = (id & 15) << 2;
            cp16(kb + (r * QP + c) * 4, Kt + r * HD + c);
            cp16(vb + (r * VP + c) * 4, Vt + r * HD + c);
        }
    };

    // Prologue: Q (into PQ region) + tile0
    {
        uint32_t qdst = sbase + PQ_OFF * 4;
        #pragma unroll
        for (int l = 0; l < 16; l++) {
            int id = tid + l * 128;
            int r = id >> 4;             // 0..127
            int c = (id & 15) << 2;
            cp16(qdst + (r * QP + c) * 4, Qg + r * HD + c);
        }
        issue_kv(0, 0);
        CP_COMMIT();
        CP_WAIT(0);
        __syncthreads();
    }

    // Preload Q fragments to registers (warp-private rows), then P may
    // overwrite the region.
    uint32_t qa[2][8][4];
    #pragma unroll
    for (int mf = 0; mf < 2; mf++) {
        int r0i = PQ_OFF + (w * 32 + mf * 16 + g) * QP;
        int r1i = r0i + 8 * QP;
        #pragma unroll
        for (int ks = 0; ks < 8; ks++) {
            const int kc = ks * 8;
            qa[mf][ks][0] = su[r0i + kc + tig];
            qa[mf][ks][1] = su[r1i + kc + tig];
            qa[mf][ks][2] = su[r0i + kc + tig + 4];
            qa[mf][ks][3] = su[r1i + kc + tig + 4];
        }
    }
    __syncwarp();

    float o[2][8][4];
    #pragma unroll
    for (int mf = 0; mf < 2; mf++)
        #pragma unroll
        for (int nf = 0; nf < 8; nf++)
            #pragma unroll
            for (int e = 0; e < 4; e++) o[mf][nf][e] = 0.f;
    float mrow[2][2] = {{-1e30f, -1e30f}, {-1e30f, -1e30f}};
    float lrow[2][2] = {{0.f, 0.f}, {0.f, 0.f}};

    for (int kt = 0; kt < TT / 64; kt++) {
        if (kt + 1 < TT / 64) {
            issue_kv((kt + 1) & 1, kt + 1);
            CP_COMMIT();
            CP_WAIT(1);
        } else {
            CP_WAIT(0);
        }
        __syncthreads();

        const uint32_t* Ks = su + KS_OFF + (kt & 1) * KSW;
        const uint32_t* Vs = su + VS_OFF + (kt & 1) * VSW;

        // S = Q @ K^T (both mf share each K fragment)
        float s[2][8][4];
        #pragma unroll
        for (int mf = 0; mf < 2; mf++)
            #pragma unroll
            for (int nf = 0; nf < 8; nf++)
                #pragma unroll
                for (int e = 0; e < 4; e++) s[mf][nf][e] = 0.f;

        #pragma unroll
        for (int ks = 0; ks < 8; ks++) {
            const int kc = ks * 8;
            #pragma unroll
            for (int nf = 0; nf < 8; nf++) {
                uint32_t kb[2];
                int rowi = (nf * 8 + g) * QP;
                kb[0] = Ks[rowi + kc + tig];
                kb[1] = Ks[rowi + kc + tig + 4];
                mma8(s[0][nf], qa[0][ks], kb);
                mma8(s[1][nf], qa[1][ks], kb);
            }
        }

        // Online softmax + P write (per mf; rows are warp-private)
        #pragma unroll
        for (int mf = 0; mf < 2; mf++) {
            float rm0 = -1e30f, rm1 = -1e30f;
            #pragma unroll
            for (int nf = 0; nf < 8; nf++) {
                rm0 = fmaxf(rm0, fmaxf(s[mf][nf][0], s[mf][nf][1]));
                rm1 = fmaxf(rm1, fmaxf(s[mf][nf][2], s[mf][nf][3]));
            }
            #pragma unroll
            for (int off = 1; off <= 2; off <<= 1) {
                rm0 = fmaxf(rm0, __shfl_xor_sync(0xffffffffu, rm0, off));
                rm1 = fmaxf(rm1, __shfl_xor_sync(0xffffffffu, rm1, off));
            }
            float mn0 = fmaxf(mrow[mf][0], rm0);
            float mn1 = fmaxf(mrow[mf][1], rm1);
            float al0 = __expf(mrow[mf][0] - mn0);
            float al1 = __expf(mrow[mf][1] - mn1);
            mrow[mf][0] = mn0; mrow[mf][1] = mn1;
            float rs0 = 0.f, rs1 = 0.f;
            #pragma unroll
            for (int nf = 0; nf < 8; nf++) {
                s[mf][nf][0] = __expf(s[mf][nf][0] - mn0);
                s[mf][nf][1] = __expf(s[mf][nf][1] - mn0);
                s[mf][nf][2] = __expf(s[mf][nf][2] - mn1);
                s[mf][nf][3] = __expf(s[mf][nf][3] - mn1);
                rs0 += s[mf][nf][0] + s[mf][nf][1];
                rs1 += s[mf][nf][2] + s[mf][nf][3];
            }
            #pragma unroll
            for (int off = 1; off <= 2; off <<= 1) {
                rs0 += __shfl_xor_sync(0xffffffffu, rs0, off);
                rs1 += __shfl_xor_sync(0xffffffffu, rs1, off);
            }
            lrow[mf][0] = lrow[mf][0] * al0 + rs0;
            lrow[mf][1] = lrow[mf][1] * al1 + rs1;
            #pragma unroll
            for (int nf = 0; nf < 8; nf++) {
                o[mf][nf][0] *= al0; o[mf][nf][1] *= al0;
                o[mf][nf][2] *= al1; o[mf][nf][3] *= al1;
            }
            // P write: STS.64 pairs (tf32-rounded)
            int pr0 = PQ_OFF + (w * 32 + mf * 16 + g) * QP;
            int pr1 = pr0 + 8 * QP;
            #pragma unroll
            for (int nf = 0; nf < 8; nf++) {
                int cb = nf * 8 + 2 * tig;
                uint2 p0 = make_uint2(tf32_of(s[mf][nf][0]), tf32_of(s[mf][nf][1]));
                uint2 p1 = make_uint2(tf32_of(s[mf][nf][2]), tf32_of(s[mf][nf][3]));
                *(uint2*)&su[pr0 + cb] = p0;
                *(uint2*)&su[pr1 + cb] = p1;
            }
        }
        __syncwarp();

        // O += P @ V
        #pragma unroll
        for (int ks = 0; ks < 8; ks++) {
            const int kc = ks * 8;
            uint32_t pa[2][4];
            #pragma unroll
            for (int mf = 0; mf < 2; mf++) {
                int r0i = PQ_OFF + (w * 32 + mf * 16 + g) * QP;
                int r1i = r0i + 8 * QP;
                pa[mf][0] = su[r0i + kc + tig];
                pa[mf][1] = su[r1i + kc + tig];
                pa[mf][2] = su[r0i + kc + tig + 4];
                pa[mf][3] = su[r1i + kc + tig + 4];
            }
            #pragma unroll
            for (int nf = 0; nf < 8; nf++) {
                uint32_t vb[2];
                vb[0] = Vs[(kc + tig) * VP + nf * 8 + g];
                vb[1] = Vs[(kc + tig + 4) * VP + nf * 8 + g];
                mma8(o[0][nf], pa[0], vb);
                mma8(o[1][nf], pa[1], vb);
            }
        }
        __syncthreads();
    }

    // Normalized, tf32-rounded output into [b][t][h*64+d]
    float* Og = g_attn + ((long)bb * TT + qb * 128) * DD + h * HD;
    #pragma unroll
    for (int mf = 0; mf < 2; mf++) {
        float inv0 = 1.f / lrow[mf][0];
        float inv1 = 1.f / lrow[mf][1];
        int r0 = w * 32 + mf * 16 + g;
        #pragma unroll
        for (int nf = 0; nf < 8; nf++) {
            int cb = nf * 8 + 2 * tig;
            float2 p0, p1;
            p0.x = __uint_as_float(tf32_of(o[mf][nf][0] * inv0));
            p0.y = __uint_as_float(tf32_of(o[mf][nf][1] * inv0));
            p1.x = __uint_as_float(tf32_of(o[mf][nf][2] * inv1));
            p1.y = __uint_as_float(tf32_of(o[mf][nf][3] * inv1));
            *(float2*)(Og + (long)r0 * DD + cb) = p0;
            *(float2*)(Og + (long)(r0 + 8) * DD + cb) = p1;
        }
    }
}

// ---------------------------------------------------------------------------
extern "C" void kernel_launch(void* const* d_in, const int* in_sizes, int n_in,
                              void* d_out, int out_size)
{
    const float* x     = (const float*)d_in[0];
    const float* w_qkv = (const float*)d_in[1];
    const float* b_qkv = (const float*)d_in[2];
    const float* w_out = (const float*)d_in[3];
    const float* b_out = (const float*)d_in[4];
    float* out = (float*)d_out;

    (void)in_sizes; (void)n_in; (void)out_size;

    float *xr, *wqkvr, *woutr, *attn_ptr;
    cudaGetSymbolAddress((void**)&xr, g_xr);
    cudaGetSymbolAddress((void**)&wqkvr, g_wqkv);
    cudaGetSymbolAddress((void**)&woutr, g_wout);
    cudaGetSymbolAddress((void**)&attn_ptr, g_attn);

    // Pre-round inputs to tf32 (RNA)
    {
        int n4 = (M1 * K1) / 4;
        round_tf32_kernel<<<(n4 + 255) / 256, 256>>>(x, xr, n4);
        n4 = (K1 * N1) / 4;
        round_tf32_kernel<<<(n4 + 255) / 256, 256>>>(w_qkv, wqkvr, n4);
        n4 = (DD * DD) / 4;
        round_tf32_kernel<<<(n4 + 255) / 256, 256>>>(w_out, woutr, n4);
    }

    const int gemm_smem = (2 * ASW + 2 * BSW) * (int)sizeof(float); // 104448
    cudaFuncSetAttribute(gemm_tc<0>, cudaFuncAttributeMaxDynamicSharedMemorySize, gemm_smem);
    cudaFuncSetAttribute(gemm_tc<1>, cudaFuncAttributeMaxDynamicSharedMemorySize, gemm_smem);

    // QKV projection + scatter
    {
        dim3 grid(N1 / 256, M1 / 128);   // 9 x 64
        gemm_tc<0><<<grid, 256, gemm_smem>>>(xr, wqkvr, b_qkv, nullptr, M1, N1, K1);
    }

    // Flash attention
    {
        int smem_bytes = SMW * (int)sizeof(float);  // 106496
        cudaFuncSetAttribute(attn_tc, cudaFuncAttributeMaxDynamicSharedMemorySize, smem_bytes);
        dim3 grid(TT / 128, HH, BB);     // 16 x 12 x 4
        attn_tc<<<grid, 128, smem_bytes>>>();
    }

    // Output projection
    {
        dim3 grid(DD / 256, M1 / 128);   // 3 x 64
        gemm_tc<1><<<grid, 256, gemm_smem>>>(attn_ptr, woutr, b_out, out, M1, DD, DD);
    }
}